// round 8
// baseline (speedup 1.0000x reference)
#include <cuda_runtime.h>
#include <cuda_fp16.h>

#define ACTIVE     32
#define HIDDEN     256
#define ACCDIM     512
#define NTHREADS   256
#define NWARPS     (NTHREADS / 32)
#define INPUTSZ    40960

__device__ __forceinline__ float satf(float x) { return __saturatef(x); }

// packed f32x2 FMA (sm_100a; ptxas never emits from C++)
__device__ __forceinline__ void fma_f32x2(unsigned long long& d,
                                          unsigned long long a,
                                          unsigned long long b) {
    asm("fma.rn.f32x2 %0, %1, %2, %0;" : "+l"(d) : "l"(a), "l"(b));
}
__device__ __forceinline__ float f32x2_hsum(unsigned long long v) {
    unsigned int lo, hi;
    asm("mov.b64 {%0,%1}, %2;" : "=r"(lo), "=r"(hi) : "l"(v));
    return __uint_as_float(lo) + __uint_as_float(hi);
}

// 12-bit packed shadow of ft_w: 40960 rows x 96 words (plane layout:
// word plane p in [0,3), lane l -> word [row*96 + p*32 + l]).
// Each lane's 3 words hold 8 columns (cols 8l..8l+7), biased q in [1,4095].
__device__ unsigned int g_ftw_q[INPUTSZ * 96];
__device__ unsigned int g_absmax_bits;
// l1_w transposed fp32: [j4][k] -> float4 (cols 4j4..4j4+3 of output row k)
__device__ float4 g_l1w_f[128 * 32];

// dynamic smem (per CTA):
//   sh_w1f : 128*32 float4 (64 KB)  transposed fp32 L1 weights
//   sh_l2t : 32*32  float  ( 4 KB)  l2_w transposed [j][k]
//   sh_acc : NWARPS*2*512 float (32 KB)
#define SMEM_W1F     (128 * 32)
#define SMEM_L2T     (32 * 32)
#define SMEM_ACC     (NWARPS * 2 * ACCDIM)
#define SMEM_BYTES   (SMEM_W1F * 16 + (SMEM_L2T + SMEM_ACC) * 4)

// ---------- prepass kernels (every call; deterministic) ----------
__global__ void init_absmax_kernel() { g_absmax_bits = 0u; }

__global__ void absmax_kernel(const float* __restrict__ ft_w, int n4)
{
    const float4* p4 = (const float4*)ft_w;
    unsigned int m = 0;
    for (int i = blockIdx.x * blockDim.x + threadIdx.x; i < n4;
         i += gridDim.x * blockDim.x) {
        float4 v = p4[i];
        m = max(m, __float_as_uint(v.x) & 0x7fffffffu);
        m = max(m, __float_as_uint(v.y) & 0x7fffffffu);
        m = max(m, __float_as_uint(v.z) & 0x7fffffffu);
        m = max(m, __float_as_uint(v.w) & 0x7fffffffu);
    }
    // warp reduce
    #pragma unroll
    for (int off = 16; off > 0; off >>= 1)
        m = max(m, __shfl_xor_sync(0xffffffffu, m, off));
    if ((threadIdx.x & 31) == 0)
        atomicMax(&g_absmax_bits, m);
}

__global__ void quantize_ftw_kernel(const float* __restrict__ ft_w)
{
    // one warp per row; lane owns cols [8l, 8l+8)
    const int warps_per_blk = NTHREADS / 32;
    const int row = blockIdx.x * warps_per_blk + (threadIdx.x >> 5);
    if (row >= INPUTSZ) return;
    const int lane = threadIdx.x & 31;

    const float s = __uint_as_float(g_absmax_bits) / 2047.0f;
    const float inv_s = 1.0f / s;

    const float4* r4 = (const float4*)(ft_w + (long)row * HIDDEN);
    float4 a = r4[2 * lane];
    float4 b = r4[2 * lane + 1];

    int q0 = __float2int_rn(a.x * inv_s) + 2048;
    int q1 = __float2int_rn(a.y * inv_s) + 2048;
    int q2 = __float2int_rn(a.z * inv_s) + 2048;
    int q3 = __float2int_rn(a.w * inv_s) + 2048;
    int q4 = __float2int_rn(b.x * inv_s) + 2048;
    int q5 = __float2int_rn(b.y * inv_s) + 2048;
    int q6 = __float2int_rn(b.z * inv_s) + 2048;
    int q7 = __float2int_rn(b.w * inv_s) + 2048;

    unsigned int w0 = (unsigned)q0 | ((unsigned)q1 << 12) | (((unsigned)q2 & 0xFFu) << 24);
    unsigned int w1 = ((unsigned)q2 >> 8) | ((unsigned)q3 << 4) | ((unsigned)q4 << 16)
                    | (((unsigned)q5 & 0xFu) << 28);
    unsigned int w2 = ((unsigned)q5 >> 4) | ((unsigned)q6 << 8) | ((unsigned)q7 << 20);

    unsigned int* dst = g_ftw_q + (long)row * 96;
    dst[lane]      = w0;
    dst[32 + lane] = w1;
    dst[64 + lane] = w2;
}

__global__ void pack_l1w_kernel(const float* __restrict__ l1_w)
{
    int i = blockIdx.x * blockDim.x + threadIdx.x;      // i = j4*32 + k
    if (i >= 128 * 32) return;
    int j4 = i >> 5, k = i & 31;
    const float* r = l1_w + k * ACCDIM + j4 * 4;
    g_l1w_f[i] = make_float4(r[0], r[1], r[2], r[3]);
}

// ---------- main fused kernel ----------
__global__ __launch_bounds__(NTHREADS, 2)
void nnue_fused_kernel(
    const int*   __restrict__ white_idx,
    const int*   __restrict__ black_idx,
    const float* __restrict__ stm,
    const float* __restrict__ ft_b,
    const float* __restrict__ l2_w,
    const float* __restrict__ l1_b,
    const float* __restrict__ l2_b,
    const float* __restrict__ l3_w,
    const float* __restrict__ l3_b,
    float*       __restrict__ out,
    int B)
{
    extern __shared__ float sm[];
    ulonglong2* sh_w1f = (ulonglong2*)sm;                 // [128][32] float4
    float* sh_l2t = sm + SMEM_W1F * 4;                    // [32][32]
    float* sh_acc = sh_l2t + SMEM_L2T;

    const int tid = threadIdx.x;

    {
        const uint4* srcw = (const uint4*)g_l1w_f;
        uint4* dstw = (uint4*)sh_w1f;
        for (int i = tid; i < SMEM_W1F; i += NTHREADS)
            dstw[i] = srcw[i];
    }
    for (int i = tid; i < SMEM_L2T; i += NTHREADS) {
        int j = i >> 5, k = i & 31;
        sh_l2t[i] = l2_w[k * 32 + j];
    }
    __syncthreads();

    const int lane  = tid & 31;
    const int warp  = tid >> 5;
    const int gwarp = blockIdx.x * NWARPS + warp;
    const int wstride = gridDim.x * NWARPS;

    float4* acc0_4 = (float4*)(sh_acc + warp * 2 * ACCDIM);   // 128 float4
    float4* acc1_4 = acc0_4 + (ACCDIM / 4);
    const ulonglong2* acc0_u2 = (const ulonglong2*)acc0_4;
    const ulonglong2* acc1_u2 = (const ulonglong2*)acc1_4;

    const float s_q = __uint_as_float(g_absmax_bits) / 2047.0f;   // dequant scale
    const float bias_off = -65536.0f * s_q;                       // -32*2048*s

    const float l1b = l1_b[lane];
    const float l2b = l2_b[lane];
    const float l3w = l3_w[lane];
    const float l3b = l3_b[0];
    // lane owns columns [8*lane, 8*lane+8); fold the Sum-q bias into ft_b
    const float4* ftb4 = (const float4*)ft_b;
    float4 fbA = ftb4[2 * lane];
    float4 fbB = ftb4[2 * lane + 1];
    fbA.x += bias_off; fbA.y += bias_off; fbA.z += bias_off; fbA.w += bias_off;
    fbB.x += bias_off; fbB.y += bias_off; fbB.z += bias_off; fbB.w += bias_off;

    const int G = B >> 1;

    for (int g = gwarp; g < G; g += wstride) {
        const int p0 = g * 2;
        const int p1 = p0 + 1;

        // ---- feature transform + select, both positions ----
        #pragma unroll
        for (int pp = 0; pp < 2; pp++) {
            const int pos = pp ? p1 : p0;
            float4* accp = pp ? acc1_4 : acc0_4;

            const int wi = white_idx[pos * ACTIVE + lane];
            const int bi = black_idx[pos * ACTIVE + lane];

            // exact integer accumulation of biased 12-bit codes
            int wa0=0,wa1=0,wa2=0,wa3=0,wa4=0,wa5=0,wa6=0,wa7=0;
            int ba0=0,ba1=0,ba2=0,ba3=0,ba4=0,ba5=0,ba6=0,ba7=0;

            #pragma unroll 4
            for (int j = 0; j < ACTIVE; j++) {
                const int iw = __shfl_sync(0xffffffffu, wi, j);
                const int ib = __shfl_sync(0xffffffffu, bi, j);
                const unsigned int* pw = g_ftw_q + (long)iw * 96;
                const unsigned int* pb = g_ftw_q + (long)ib * 96;
                const unsigned int x0 = __ldcg(pw + lane);
                const unsigned int x1 = __ldcg(pw + 32 + lane);
                const unsigned int x2 = __ldcg(pw + 64 + lane);
                const unsigned int y0 = __ldcg(pb + lane);
                const unsigned int y1 = __ldcg(pb + 32 + lane);
                const unsigned int y2 = __ldcg(pb + 64 + lane);

                wa0 +=  x0        & 0xFFFu;
                wa1 += (x0 >> 12) & 0xFFFu;
                wa2 += (x0 >> 24) + ((x1 & 0xFu) << 8);
                wa3 += (x1 >>  4) & 0xFFFu;
                wa4 += (x1 >> 16) & 0xFFFu;
                wa5 += (x1 >> 28) + ((x2 & 0xFFu) << 4);
                wa6 += (x2 >>  8) & 0xFFFu;
                wa7 +=  x2 >> 20;

                ba0 +=  y0        & 0xFFFu;
                ba1 += (y0 >> 12) & 0xFFFu;
                ba2 += (y0 >> 24) + ((y1 & 0xFu) << 8);
                ba3 += (y1 >>  4) & 0xFFFu;
                ba4 += (y1 >> 16) & 0xFFFu;
                ba5 += (y1 >> 28) + ((y2 & 0xFFu) << 4);
                ba6 += (y2 >>  8) & 0xFFFu;
                ba7 +=  y2 >> 20;
            }

            // dequant + bias + clip
            float4 cw0 = make_float4(satf(fmaf((float)wa0, s_q, fbA.x)),
                                     satf(fmaf((float)wa1, s_q, fbA.y)),
                                     satf(fmaf((float)wa2, s_q, fbA.z)),
                                     satf(fmaf((float)wa3, s_q, fbA.w)));
            float4 cw1 = make_float4(satf(fmaf((float)wa4, s_q, fbB.x)),
                                     satf(fmaf((float)wa5, s_q, fbB.y)),
                                     satf(fmaf((float)wa6, s_q, fbB.z)),
                                     satf(fmaf((float)wa7, s_q, fbB.w)));
            float4 cb0 = make_float4(satf(fmaf((float)ba0, s_q, fbA.x)),
                                     satf(fmaf((float)ba1, s_q, fbA.y)),
                                     satf(fmaf((float)ba2, s_q, fbA.z)),
                                     satf(fmaf((float)ba3, s_q, fbA.w)));
            float4 cb1 = make_float4(satf(fmaf((float)ba4, s_q, fbB.x)),
                                     satf(fmaf((float)ba5, s_q, fbB.y)),
                                     satf(fmaf((float)ba6, s_q, fbB.z)),
                                     satf(fmaf((float)ba7, s_q, fbB.w)));

            const float s = stm[pos];
            const bool wfirst = (s > 0.5f);
            accp[2*lane]          = wfirst ? cw0 : cb0;
            accp[2*lane + 1]      = wfirst ? cw1 : cb1;
            accp[64 + 2*lane]     = wfirst ? cb0 : cw0;
            accp[64 + 2*lane + 1] = wfirst ? cb1 : cw1;
        }
        __syncwarp();

        // ---- L1: lane k computes output k for both positions (f32x2 FMA) ----
        unsigned long long q00 = 0ull, q01 = 0ull;
        unsigned long long q10 = 0ull, q11 = 0ull;
        const ulonglong2* wrow = sh_w1f + lane;
        #pragma unroll 4
        for (int j4 = 0; j4 < 128; j4++) {
            const ulonglong2 wv = wrow[j4 * 32];     // conflict-free
            const ulonglong2 a0 = acc0_u2[j4];       // broadcast
            const ulonglong2 a1 = acc1_u2[j4];       // broadcast
            fma_f32x2(q00, a0.x, wv.x);
            fma_f32x2(q01, a0.y, wv.y);
            fma_f32x2(q10, a1.x, wv.x);
            fma_f32x2(q11, a1.y, wv.y);
        }
        const float x1_0 = satf(f32x2_hsum(q00) + f32x2_hsum(q01) + l1b);
        const float x1_1 = satf(f32x2_hsum(q10) + f32x2_hsum(q11) + l1b);
        __syncwarp();   // acc reads done before next pair's stores

        // ---- L2 + L3 ----
        #pragma unroll
        for (int pp = 0; pp < 2; pp++) {
            const float x1 = pp ? x1_1 : x1_0;
            float s2 = l2b;
            #pragma unroll
            for (int j = 0; j < 32; j++) {
                const float xj = __shfl_sync(0xffffffffu, x1, j);
                s2 += xj * sh_l2t[j * 32 + lane];
            }
            const float x2 = satf(s2);
            float p = x2 * l3w;
            #pragma unroll
            for (int off = 16; off > 0; off >>= 1)
                p += __shfl_xor_sync(0xffffffffu, p, off);
            if (lane == 0)
                out[pp ? p1 : p0] = p + l3b;
        }
    }
}

extern "C" void kernel_launch(void* const* d_in, const int* in_sizes, int n_in,
                              void* d_out, int out_size)
{
    const int*   white_idx = (const int*)  d_in[0];
    const int*   black_idx = (const int*)  d_in[1];
    const float* stm       = (const float*)d_in[2];
    const float* ft_w      = (const float*)d_in[3];
    const float* ft_b      = (const float*)d_in[4];
    const float* l1_w      = (const float*)d_in[5];
    const float* l1_b      = (const float*)d_in[6];
    const float* l2_w      = (const float*)d_in[7];
    const float* l2_b      = (const float*)d_in[8];
    const float* l3_w      = (const float*)d_in[9];
    const float* l3_b      = (const float*)d_in[10];
    float* out = (float*)d_out;

    const int B = in_sizes[0] / ACTIVE;

    // prepass: exact absmax -> 12-bit quantized table + packed L1 weights
    init_absmax_kernel<<<1, 1>>>();
    const int n4 = INPUTSZ * HIDDEN / 4;
    absmax_kernel<<<2048, NTHREADS>>>(ft_w, n4);
    quantize_ftw_kernel<<<INPUTSZ / (NTHREADS / 32), NTHREADS>>>(ft_w);
    pack_l1w_kernel<<<(128 * 32 + 255) / 256, 256>>>(l1_w);

    cudaFuncSetAttribute(nnue_fused_kernel,
                         cudaFuncAttributeMaxDynamicSharedMemorySize,
                         (int)SMEM_BYTES);
    const int grid = 296;   // 2 CTAs/SM on 148 SMs
    nnue_fused_kernel<<<grid, NTHREADS, SMEM_BYTES>>>(
        white_idx, black_idx, stm, ft_b, l2_w,
        l1_b, l2_b, l3_w, l3_b, out, B);
}

// round 9
// speedup vs baseline: 1.2463x; 1.2463x over previous
#include <cuda_runtime.h>
#include <cuda_fp16.h>

#define ACTIVE     32
#define HIDDEN     256
#define ACCDIM     512
#define NTHREADS   256
#define NWARPS     (NTHREADS / 32)
#define INPUTSZ    40960

__device__ __forceinline__ unsigned int h2_to_u32(__half2 h) {
    return *reinterpret_cast<unsigned int*>(&h);
}
__device__ __forceinline__ __half2 u32_to_h2(unsigned int u) {
    return *reinterpret_cast<__half2*>(&u);
}
__device__ __forceinline__ float satf(float x) { return __saturatef(x); }

// packed f32x2 FMA (sm_100a; ptxas never emits from C++)
__device__ __forceinline__ void fma_f32x2(unsigned long long& d,
                                          unsigned long long a,
                                          unsigned long long b) {
    asm("fma.rn.f32x2 %0, %1, %2, %0;" : "+l"(d) : "l"(a), "l"(b));
}
__device__ __forceinline__ float f32x2_hsum(unsigned long long v) {
    unsigned int lo, hi;
    asm("mov.b64 {%0,%1}, %2;" : "=r"(lo), "=r"(hi) : "l"(v));
    return __uint_as_float(lo) + __uint_as_float(hi);
}

// fp16 shadow of ft_w: 40960 rows x 256 halves = 512B/row = 32 uint4 per row.
__device__ uint4 g_ftw_h[INPUTSZ * 32];
// l1_w transposed fp32: [j4][k] -> float4 (cols 4j4..4j4+3 of output row k)
__device__ float4 g_l1w_f[128 * 32];

// dynamic smem (per CTA):
//   sh_w1f : 128*32 float4 (64 KB)  transposed fp32 L1 weights
//   sh_l2t : 32*32  float  ( 4 KB)  l2_w transposed [j][k]
//   sh_acc : NWARPS*2*512 float (32 KB)
#define SMEM_W1F     (128 * 32)
#define SMEM_L2T     (32 * 32)
#define SMEM_ACC     (NWARPS * 2 * ACCDIM)
#define SMEM_BYTES   (SMEM_W1F * 16 + (SMEM_L2T + SMEM_ACC) * 4)

// ---------- merged prepass (ONE launch; every call; deterministic) ----------
__global__ void prepass_kernel(const float* __restrict__ ft_w,
                               const float* __restrict__ l1_w, int n_u4)
{
    int i = blockIdx.x * blockDim.x + threadIdx.x;
    if (i < n_u4) {                       // fp16 table convert (one uint4 = 8 halves)
        const float4* src = (const float4*)ft_w;
        float4 a = src[2 * i];
        float4 b = src[2 * i + 1];
        uint4 o;
        o.x = h2_to_u32(__floats2half2_rn(a.x, a.y));
        o.y = h2_to_u32(__floats2half2_rn(a.z, a.w));
        o.z = h2_to_u32(__floats2half2_rn(b.x, b.y));
        o.w = h2_to_u32(__floats2half2_rn(b.z, b.w));
        g_ftw_h[i] = o;
    }
    if (blockIdx.x == 0) {                // l1_w transpose-pack (4096 float4)
        for (int t = threadIdx.x; t < 128 * 32; t += NTHREADS) {
            int j4 = t >> 5, k = t & 31;
            const float* r = l1_w + k * ACCDIM + j4 * 4;
            g_l1w_f[t] = make_float4(r[0], r[1], r[2], r[3]);
        }
    }
}

// ---------- main fused kernel ----------
__global__ __launch_bounds__(NTHREADS, 2)
void nnue_fused_kernel(
    const int*   __restrict__ white_idx,
    const int*   __restrict__ black_idx,
    const float* __restrict__ stm,
    const float* __restrict__ ft_b,
    const float* __restrict__ l2_w,
    const float* __restrict__ l1_b,
    const float* __restrict__ l2_b,
    const float* __restrict__ l3_w,
    const float* __restrict__ l3_b,
    float*       __restrict__ out,
    int B)
{
    extern __shared__ float sm[];
    ulonglong2* sh_w1f = (ulonglong2*)sm;                 // [128][32] float4
    float* sh_l2t = sm + SMEM_W1F * 4;                    // [32][32]
    float* sh_acc = sh_l2t + SMEM_L2T;

    const int tid = threadIdx.x;

    {
        const uint4* srcw = (const uint4*)g_l1w_f;
        uint4* dstw = (uint4*)sh_w1f;
        for (int i = tid; i < SMEM_W1F; i += NTHREADS)
            dstw[i] = srcw[i];
    }
    for (int i = tid; i < SMEM_L2T; i += NTHREADS) {
        int j = i >> 5, k = i & 31;
        sh_l2t[i] = l2_w[k * 32 + j];
    }
    __syncthreads();

    const int lane  = tid & 31;
    const int warp  = tid >> 5;
    const int gwarp = blockIdx.x * NWARPS + warp;
    const int wstride = gridDim.x * NWARPS;

    float4* acc0_4 = (float4*)(sh_acc + warp * 2 * ACCDIM);   // 128 float4
    float4* acc1_4 = acc0_4 + (ACCDIM / 4);
    const ulonglong2* acc0_u2 = (const ulonglong2*)acc0_4;
    const ulonglong2* acc1_u2 = (const ulonglong2*)acc1_4;

    const float l1b = l1_b[lane];
    const float l2b = l2_b[lane];
    const float l3w = l3_w[lane];
    const float l3b = l3_b[0];
    // lane owns columns [8*lane, 8*lane+8)
    const float4* ftb4 = (const float4*)ft_b;
    const float4 fbA = ftb4[2 * lane];
    const float4 fbB = ftb4[2 * lane + 1];

    const int G = B >> 1;

    for (int g = gwarp; g < G; g += wstride) {
        const int p0 = g * 2;
        const int p1 = p0 + 1;

        // ---- feature transform + select, both positions ----
        #pragma unroll
        for (int pp = 0; pp < 2; pp++) {
            const int pos = pp ? p1 : p0;
            float4* accp = pp ? acc1_4 : acc0_4;

            const int* wrow_idx = white_idx + pos * ACTIVE;
            const int* brow_idx = black_idx + pos * ACTIVE;

            float w0=0.f,w1=0.f,w2=0.f,w3=0.f,w4=0.f,w5=0.f,w6=0.f,w7=0.f;
            float b0=0.f,b1=0.f,b2=0.f,b3=0.f,b4=0.f,b5=0.f,b6=0.f,b7=0.f;

            const __half2 hz = u32_to_h2(0u);

            // 8 chunks of 4 indices; fp16 HADD2 within chunk, fp32 combine.
            // Index fetch = broadcast LDG.32 (L1-hit, 1 wf) instead of SHFL (MIO).
            #pragma unroll
            for (int c = 0; c < 8; c++) {
                __half2 sw0=hz, sw1=hz, sw2=hz, sw3=hz;
                __half2 sb0=hz, sb1=hz, sb2=hz, sb3=hz;
                #pragma unroll
                for (int u = 0; u < 4; u++) {
                    const int j = c * 4 + u;
                    const int iw = __ldg(wrow_idx + j);   // broadcast, L1-resident
                    const int ib = __ldg(brow_idx + j);
                    const uint4 rw = __ldg(&g_ftw_h[(long)iw * 32 + lane]);
                    const uint4 rb = __ldg(&g_ftw_h[(long)ib * 32 + lane]);
                    sw0 = __hadd2(sw0, u32_to_h2(rw.x));
                    sw1 = __hadd2(sw1, u32_to_h2(rw.y));
                    sw2 = __hadd2(sw2, u32_to_h2(rw.z));
                    sw3 = __hadd2(sw3, u32_to_h2(rw.w));
                    sb0 = __hadd2(sb0, u32_to_h2(rb.x));
                    sb1 = __hadd2(sb1, u32_to_h2(rb.y));
                    sb2 = __hadd2(sb2, u32_to_h2(rb.z));
                    sb3 = __hadd2(sb3, u32_to_h2(rb.w));
                }
                {
                    float2 f0 = __half22float2(sw0);
                    float2 f1 = __half22float2(sw1);
                    float2 f2 = __half22float2(sw2);
                    float2 f3 = __half22float2(sw3);
                    w0 += f0.x; w1 += f0.y; w2 += f1.x; w3 += f1.y;
                    w4 += f2.x; w5 += f2.y; w6 += f3.x; w7 += f3.y;
                }
                {
                    float2 f0 = __half22float2(sb0);
                    float2 f1 = __half22float2(sb1);
                    float2 f2 = __half22float2(sb2);
                    float2 f3 = __half22float2(sb3);
                    b0 += f0.x; b1 += f0.y; b2 += f1.x; b3 += f1.y;
                    b4 += f2.x; b5 += f2.y; b6 += f3.x; b7 += f3.y;
                }
            }

            float4 cw0 = make_float4(satf(w0+fbA.x), satf(w1+fbA.y),
                                     satf(w2+fbA.z), satf(w3+fbA.w));
            float4 cw1 = make_float4(satf(w4+fbB.x), satf(w5+fbB.y),
                                     satf(w6+fbB.z), satf(w7+fbB.w));
            float4 cb0 = make_float4(satf(b0+fbA.x), satf(b1+fbA.y),
                                     satf(b2+fbA.z), satf(b3+fbA.w));
            float4 cb1 = make_float4(satf(b4+fbB.x), satf(b5+fbB.y),
                                     satf(b6+fbB.z), satf(b7+fbB.w));

            const float s = stm[pos];
            const bool wfirst = (s > 0.5f);
            accp[2*lane]          = wfirst ? cw0 : cb0;
            accp[2*lane + 1]      = wfirst ? cw1 : cb1;
            accp[64 + 2*lane]     = wfirst ? cb0 : cw0;
            accp[64 + 2*lane + 1] = wfirst ? cb1 : cw1;
        }
        __syncwarp();

        // ---- L1: lane k computes output k for both positions (f32x2 FMA) ----
        unsigned long long q00 = 0ull, q01 = 0ull;
        unsigned long long q10 = 0ull, q11 = 0ull;
        const ulonglong2* wrow = sh_w1f + lane;
        #pragma unroll 4
        for (int j4 = 0; j4 < 128; j4++) {
            const ulonglong2 wv = wrow[j4 * 32];     // conflict-free
            const ulonglong2 a0 = acc0_u2[j4];       // broadcast
            const ulonglong2 a1 = acc1_u2[j4];       // broadcast
            fma_f32x2(q00, a0.x, wv.x);
            fma_f32x2(q01, a0.y, wv.y);
            fma_f32x2(q10, a1.x, wv.x);
            fma_f32x2(q11, a1.y, wv.y);
        }
        const float x1_0 = satf(f32x2_hsum(q00) + f32x2_hsum(q01) + l1b);
        const float x1_1 = satf(f32x2_hsum(q10) + f32x2_hsum(q11) + l1b);
        __syncwarp();   // acc reads done before next pair's stores

        // ---- L2 + L3 ----
        #pragma unroll
        for (int pp = 0; pp < 2; pp++) {
            const float x1 = pp ? x1_1 : x1_0;
            float s2 = l2b;
            #pragma unroll
            for (int j = 0; j < 32; j++) {
                const float xj = __shfl_sync(0xffffffffu, x1, j);
                s2 += xj * sh_l2t[j * 32 + lane];
            }
            const float x2 = satf(s2);
            float p = x2 * l3w;
            #pragma unroll
            for (int off = 16; off > 0; off >>= 1)
                p += __shfl_xor_sync(0xffffffffu, p, off);
            if (lane == 0)
                out[pp ? p1 : p0] = p + l3b;
        }
    }
}

extern "C" void kernel_launch(void* const* d_in, const int* in_sizes, int n_in,
                              void* d_out, int out_size)
{
    const int*   white_idx = (const int*)  d_in[0];
    const int*   black_idx = (const int*)  d_in[1];
    const float* stm       = (const float*)d_in[2];
    const float* ft_w      = (const float*)d_in[3];
    const float* ft_b      = (const float*)d_in[4];
    const float* l1_w      = (const float*)d_in[5];
    const float* l1_b      = (const float*)d_in[6];
    const float* l2_w      = (const float*)d_in[7];
    const float* l2_b      = (const float*)d_in[8];
    const float* l3_w      = (const float*)d_in[9];
    const float* l3_b      = (const float*)d_in[10];
    float* out = (float*)d_out;

    const int B = in_sizes[0] / ACTIVE;

    // single prepass launch -> 2 launches/call total, so ncu -s 5 -c 1
    // captures the MAIN kernel (launch #6)
    const int n_u4 = INPUTSZ * 32;
    prepass_kernel<<<(n_u4 + NTHREADS - 1) / NTHREADS, NTHREADS>>>(ft_w, l1_w, n_u4);

    cudaFuncSetAttribute(nnue_fused_kernel,
                         cudaFuncAttributeMaxDynamicSharedMemorySize,
                         (int)SMEM_BYTES);
    const int grid = 296;   // 2 CTAs/SM on 148 SMs
    nnue_fused_kernel<<<grid, NTHREADS, SMEM_BYTES>>>(
        white_idx, black_idx, stm, ft_b, l2_w,
        l1_b, l2_b, l3_w, l3_b, out, B);
}